// round 17
// baseline (speedup 1.0000x reference)
#include <cuda_runtime.h>
#include <math_constants.h>
#include <cstdint>

#define H 1024
#define V 50257
#define L 12
#define TILES ((V + 7) / 8)          // 6283 blocks in k3, 8 rows each

// ---- device scratch (no allocations allowed), 16B-aligned ----
__device__ __align__(16) float g_xin[2 * H];   // [embedded ; attn_applied]
__device__ __align__(16) float g_x[H];         // relu(combine) output
__device__ __align__(16) float g_h[H];         // h_new (aligned copy)
__device__ float g_sum;                        // global sum(exp(logit)) accumulator

__device__ __forceinline__ float warp_sum(float v) {
#pragma unroll
    for (int o = 16; o; o >>= 1) v += __shfl_xor_sync(0xffffffffu, v, o);
    return v;
}

__device__ __forceinline__ float4 ldcs4(const float4* p) { return __ldcs(p); }

// PDL controls (sm_90+)
__device__ __forceinline__ void pdl_trigger() {
#if __CUDA_ARCH__ >= 900
    asm volatile("griddepcontrol.launch_dependents;");
#endif
}
__device__ __forceinline__ void pdl_wait() {
#if __CUDA_ARCH__ >= 900
    asm volatile("griddepcontrol.wait;" ::: "memory");
#endif
}
__device__ __forceinline__ void l2_prefetch(const void* p) {
    asm volatile("prefetch.global.L2 [%0];" :: "l"(p));
}

// ============================================================
// Kernel 0: embedding + attention softmax + applied context.
// Single block, 384 threads. Writes g_xin = [emb ; applied].
// Triggers dependents at entry so k1/k2/k3 begin prefetching.
// ============================================================
__global__ void k0_attn(const int* input,
                        const float* __restrict__ h_hidden,
                        const float* __restrict__ enc,
                        const float* __restrict__ emb,
                        const float* __restrict__ attn_W,
                        const float* __restrict__ attn_b,
                        float* __restrict__ attnw_out) {
    __shared__ __align__(16) float s_in[2 * H];
    __shared__ float s_logit[L];
    __shared__ float s_w[L];
    const int tid = threadIdx.x;
    pdl_trigger();

    if (tid == 0) g_sum = 0.f;      // reset accumulator for this replay

    const int idx = input[0];       // low 32 bits of LE int64 index
    const float* e = emb + (size_t)idx * H;
    for (int i = tid; i < H; i += 384) {
        float v = e[i];
        s_in[i] = v;
        g_xin[i] = v;
        s_in[H + i] = h_hidden[i];
    }
    __syncthreads();

    const int w = tid >> 5, lane = tid & 31;
    if (w < L) {
        const float4* row = (const float4*)(attn_W + (size_t)w * 2 * H);
        const float4* s4 = (const float4*)s_in;
        float acc = 0.f;
#pragma unroll
        for (int t = 0; t < 16; t++) {
            float4 a = row[lane + 32 * t];
            float4 b = s4[lane + 32 * t];
            acc += a.x * b.x + a.y * b.y + a.z * b.z + a.w * b.w;
        }
        acc = warp_sum(acc);
        if (lane == 0) s_logit[w] = acc + attn_b[w];
    }
    __syncthreads();

    if (tid == 0) {
        float m = -1e30f;
#pragma unroll
        for (int l = 0; l < L; l++) m = fmaxf(m, s_logit[l]);
        float s = 0.f;
#pragma unroll
        for (int l = 0; l < L; l++) { float ex = expf(s_logit[l] - m); s_w[l] = ex; s += ex; }
        float inv = 1.f / s;
#pragma unroll
        for (int l = 0; l < L; l++) { s_w[l] *= inv; attnw_out[l] = s_w[l]; }
    }
    __syncthreads();

    for (int j = tid; j < H; j += 384) {
        float acc = 0.f;
#pragma unroll
        for (int l = 0; l < L; l++) acc += s_w[l] * enc[l * H + j];
        g_xin[H + j] = acc;
    }
}

// ============================================================
// Kernel 1: combine matvec. 128 blocks x 256, warp-per-row.
// PRE-WAIT: prefetch this block's 8 comb_W rows (64KB) into L2.
// POST-WAIT: dot from (mostly) L2 against g_xin.
// ============================================================
__global__ void __launch_bounds__(256, 6)
k1_comb(const float* __restrict__ comb_W,
        const float* __restrict__ comb_b) {
    __shared__ __align__(16) float4 s_v[512];    // g_xin, 2048 floats
    const int tid = threadIdx.x;
    const int w = tid >> 5, lane = tid & 31;
    const int r = blockIdx.x * 8 + w;
    pdl_trigger();

    // pre-wait: prefetch 8KB row per warp (2 x 128B per lane)
    {
        const char* base = (const char*)(comb_W + (size_t)r * 2 * H);
        l2_prefetch(base + lane * 128);
        l2_prefetch(base + 4096 + lane * 128);
    }

    pdl_wait();                       // k0's g_xin now visible
    const float4* x4 = (const float4*)g_xin;
    s_v[tid] = x4[tid];
    s_v[tid + 256] = x4[tid + 256];
    __syncthreads();

    const float4* row = (const float4*)(comb_W + (size_t)r * 2 * H);
    float acc = 0.f;
#pragma unroll
    for (int t = 0; t < 16; t++) {
        float4 a = ldcs4(row + lane + 32 * t);
        float4 b = s_v[lane + 32 * t];
        acc += a.x * b.x + a.y * b.y + a.z * b.z + a.w * b.w;
    }
    acc = warp_sum(acc);
    if (lane == 0) g_x[r] = fmaxf(acc + comb_b[r], 0.f);
}

// ============================================================
// Kernel 2: full LSTM (hh + ih gates + cell). 512 blocks x 256.
// Warp w handles (unit u = w>>2, gate g = w&3) for units 2b,2b+1.
// PRE-WAIT: hh dot (only needs h_hidden) + W_ih L2 prefetch —
//   overlaps the whole k0+k1 window.
// POST-WAIT: ih dot (needs g_x), gate sum, cell math in-block.
// ============================================================
__global__ void __launch_bounds__(256, 6)
k2_lstm(const float* __restrict__ h_hidden,
        const float* __restrict__ c_hidden,
        const float* __restrict__ W_ih,
        const float* __restrict__ W_hh,
        const float* __restrict__ b_ih,
        const float* __restrict__ b_hh,
        float* __restrict__ h_new,
        float* __restrict__ c_new) {
    __shared__ __align__(16) float4 s_h[256];     // h0
    __shared__ __align__(16) float4 s_x[256];     // g_x (post-wait)
    __shared__ float s_gate[8];                   // [unit][gate]
    const int tid = threadIdx.x;
    const int w = tid >> 5, lane = tid & 31;
    const int u = w >> 2;                 // 0..1 local unit
    const int g = w & 3;                  // gate index
    const int j = blockIdx.x * 2 + u;     // hidden unit
    const int r = g * H + j;              // gate row
    pdl_trigger();

    // ---- pre-wait: hh dot + prefetch ih row ----
    s_h[tid] = ((const float4*)h_hidden)[tid];
    {
        const char* ih_base = (const char*)(W_ih + (size_t)r * H);
        l2_prefetch(ih_base + lane * 128);       // 32 x 128B = 4KB row
    }
    __syncthreads();

    const float4* hrow = (const float4*)(W_hh + (size_t)r * H);
    float acc_hh = 0.f;
#pragma unroll
    for (int t = 0; t < 8; t++) {
        float4 a = ldcs4(hrow + lane + 32 * t);
        float4 b = s_h[lane + 32 * t];
        acc_hh += a.x * b.x + a.y * b.y + a.z * b.z + a.w * b.w;
    }

    // ---- wait for k1's g_x ----
    pdl_wait();
    s_x[tid] = ((const float4*)g_x)[tid];
    __syncthreads();

    const float4* irow = (const float4*)(W_ih + (size_t)r * H);
    float acc_ih = 0.f;
#pragma unroll
    for (int t = 0; t < 8; t++) {
        float4 a = ldcs4(irow + lane + 32 * t);
        float4 b = s_x[lane + 32 * t];
        acc_ih += a.x * b.x + a.y * b.y + a.z * b.z + a.w * b.w;
    }
    float gate = warp_sum(acc_ih + acc_hh);
    if (lane == 0) s_gate[u * 4 + g] = gate + b_ih[r] + b_hh[r];
    __syncthreads();

    if (tid < 2) {
        const int jj = blockIdx.x * 2 + tid;
        float gi = s_gate[tid * 4 + 0];
        float gf = s_gate[tid * 4 + 1];
        float gg = s_gate[tid * 4 + 2];
        float go = s_gate[tid * 4 + 3];
        float si = 1.f / (1.f + expf(-gi));
        float sf = 1.f / (1.f + expf(-gf));
        float so = 1.f / (1.f + expf(-go));
        float c = sf * c_hidden[jj] + si * tanhf(gg);
        float h = so * tanhf(c);
        c_new[jj] = c;
        h_new[jj] = h;
        g_h[jj] = h;
    }
}

// ============================================================
// Kernel 3: output projection, 8 rows/block, warp-per-row.
// PRE-WAIT: prefetch this block's 32KB out_W tile into L2.
// Epilogue: fire-and-forget REDG into g_sum.
// ============================================================
__global__ void k3_out(const float* __restrict__ out_W,
                       const float* __restrict__ out_b,
                       float* __restrict__ logits) {
    __shared__ __align__(16) float4 s_h[256];
    __shared__ float s_l[8];
    const int tid = threadIdx.x;
    const int w = tid >> 5, lane = tid & 31;
    const int r = blockIdx.x * 8 + w;
    pdl_trigger();

    if (r < V) {
        const char* base = (const char*)(out_W + (size_t)r * H);
        l2_prefetch(base + lane * 128);  // 32 lanes cover the 4KB row
    }

    pdl_wait();                          // k2's g_h now visible
    s_h[tid] = ((const float4*)g_h)[tid];
    __syncthreads();

    float l = -CUDART_INF_F;
    if (r < V) {
        const float4* row = (const float4*)(out_W + (size_t)r * H);
        float acc = 0.f;
#pragma unroll
        for (int t = 0; t < 8; t++) {
            float4 a = ldcs4(row + lane + 32 * t);
            float4 b = s_h[lane + 32 * t];
            acc += a.x * b.x + a.y * b.y + a.z * b.z + a.w * b.w;
        }
        acc = warp_sum(acc);
        if (lane == 0) {
            l = acc + out_b[r];
            logits[r] = l;
        }
    }
    if (lane == 0) s_l[w] = l;
    __syncthreads();
    if (tid == 0) {
        float s = 0.f;
#pragma unroll
        for (int i = 0; i < 8; i++) {
            float v = s_l[i];
            if (v != -CUDART_INF_F) s += expf(v);
        }
        atomicAdd(&g_sum, s);            // REDG: no return value, no fence
    }
}

// ============================================================
// Kernel 4: logp[i] = logits[i] - log(g_sum). PDL consumer.
// ============================================================
__global__ void k4_sub(float* __restrict__ logp) {
    __shared__ float s_lse;
    const int tid = threadIdx.x;
    pdl_wait();
    if (tid == 0) s_lse = logf(g_sum);
    __syncthreads();
    const float lse = s_lse;
    const int i = blockIdx.x * 256 + tid;
    if (i < V) logp[i] -= lse;
}

// ============================================================
static inline void launch_pdl(void* fn, dim3 grid, dim3 block, void** args) {
    cudaLaunchAttribute attr[1];
    attr[0].id = cudaLaunchAttributeProgrammaticStreamSerialization;
    attr[0].val.programmaticStreamSerializationAllowed = 1;
    cudaLaunchConfig_t cfg = {};
    cfg.gridDim = grid;
    cfg.blockDim = block;
    cfg.dynamicSmemBytes = 0;
    cfg.stream = 0;
    cfg.attrs = attr;
    cfg.numAttrs = 1;
    cudaLaunchKernelExC(&cfg, fn, args);
}

extern "C" void kernel_launch(void* const* d_in, const int* in_sizes, int n_in,
                              void* d_out, int out_size) {
    const int*   input   = (const int*)  d_in[0];
    const float* h_hid   = (const float*)d_in[1];
    const float* c_hid   = (const float*)d_in[2];
    const float* enc     = (const float*)d_in[3];
    const float* emb     = (const float*)d_in[4];
    const float* attn_W  = (const float*)d_in[5];
    const float* attn_b  = (const float*)d_in[6];
    const float* comb_W  = (const float*)d_in[7];
    const float* comb_b  = (const float*)d_in[8];
    const float* W_ih    = (const float*)d_in[9];
    const float* W_hh    = (const float*)d_in[10];
    const float* b_ih    = (const float*)d_in[11];
    const float* b_hh    = (const float*)d_in[12];
    const float* out_W   = (const float*)d_in[13];
    const float* out_b   = (const float*)d_in[14];

    float* out   = (float*)d_out;
    float* logp  = out;                 // [V]
    float* h_new = out + V;             // [H]
    float* c_new = out + V + H;         // [H]
    float* attnw = out + V + 2 * H;     // [L]

    k0_attn<<<1, 384>>>(input, h_hid, enc, emb, attn_W, attn_b, attnw);
    {
        void* args[] = { (void*)&comb_W, (void*)&comb_b };
        launch_pdl((void*)k1_comb, dim3(128), dim3(256), args);
    }
    {
        void* args[] = { (void*)&h_hid, (void*)&c_hid, (void*)&W_ih, (void*)&W_hh,
                         (void*)&b_ih, (void*)&b_hh, (void*)&h_new, (void*)&c_new };
        launch_pdl((void*)k2_lstm, dim3(512), dim3(256), args);
    }
    {
        void* args[] = { (void*)&out_W, (void*)&out_b, (void*)&logp };
        launch_pdl((void*)k3_out, dim3(TILES), dim3(256), args);
    }
    {
        void* args[] = { (void*)&logp };
        launch_pdl((void*)k4_sub, dim3((V + 255) / 256), dim3(256), args);
    }
}